// round 2
// baseline (speedup 1.0000x reference)
#include <cuda_runtime.h>
#include <cstdint>

// Problem constants
#define M_Q 2048          // rows of Q (and K)
#define DV  1024          // model dim
#define NH  16            // number of heads (DIM_SPLIT)
#define HD  64            // head dim (NUM_HEADS in the module quirk)

// Scratch (device globals: allocation-free)
__device__ float g_q[M_Q * DV];
__device__ float g_k[M_Q * DV];
__device__ float g_v[M_Q * DV];
__device__ float g_attn[M_Q * DV];

__device__ __forceinline__ float f2tf(float x) {
    uint32_t r;
    asm("cvt.rna.tf32.f32 %0, %1;" : "=r"(r) : "f"(x));
    return __uint_as_float(r);
}

__device__ __forceinline__ void mma_m16n8k8(float (&d)[4],
                                            const uint32_t (&a)[4],
                                            uint32_t b0, uint32_t b1) {
    asm volatile(
        "mma.sync.aligned.m16n8k8.row.col.f32.tf32.tf32.f32 "
        "{%0,%1,%2,%3}, {%4,%5,%6,%7}, {%8,%9}, {%0,%1,%2,%3};\n"
        : "+f"(d[0]), "+f"(d[1]), "+f"(d[2]), "+f"(d[3])
        : "r"(a[0]), "r"(a[1]), "r"(a[2]), "r"(a[3]), "r"(b0), "r"(b1));
}

// ---------------------------------------------------------------------------
// GEMM: C[M,N] = epilogue(A[M,K] @ W[N,K]^T + bias[N])
// epilogue: relu==0 -> C = acc + bias
//           relu==1 -> C = resid + max(acc + bias, 0)
// BM=128, BN=64, BK=32; 256 threads, warp grid 4(M) x 2(N), warp tile 32x32
// ---------------------------------------------------------------------------
#define BM 128
#define BN 64
#define BK 32
#define LDA 36   // BK + 4 pad: frag LDS conflict-free, 16B-aligned float4 stores

__global__ __launch_bounds__(256) void gemm_tf32(
    const float* __restrict__ A, const float* __restrict__ W,
    const float* __restrict__ bias, float* __restrict__ C,
    const float* __restrict__ resid, int M, int N, int K, int relu)
{
    __shared__ float As[BM][LDA];
    __shared__ float Bs[BN][LDA];

    const int tid  = threadIdx.x;
    const int lane = tid & 31;
    const int warp = tid >> 5;
    const int wm = warp >> 1;     // 0..3
    const int wn = warp & 1;      // 0..1
    const int bm0 = blockIdx.y * BM;
    const int bn0 = blockIdx.x * BN;

    float acc[2][4][4];
    #pragma unroll
    for (int mi = 0; mi < 2; mi++)
        #pragma unroll
        for (int ni = 0; ni < 4; ni++)
            #pragma unroll
            for (int e = 0; e < 4; e++) acc[mi][ni][e] = 0.f;

    const int lr = tid >> 3;            // 0..31
    const int lc = (tid & 7) << 2;      // 0..28 step 4

    for (int k0 = 0; k0 < K; k0 += BK) {
        // A tile: 128x32
        #pragma unroll
        for (int r = 0; r < 4; r++) {
            const float4 v = *reinterpret_cast<const float4*>(
                A + (size_t)(bm0 + lr + r * 32) * K + k0 + lc);
            As[lr + r * 32][lc + 0] = f2tf(v.x);
            As[lr + r * 32][lc + 1] = f2tf(v.y);
            As[lr + r * 32][lc + 2] = f2tf(v.z);
            As[lr + r * 32][lc + 3] = f2tf(v.w);
        }
        // W tile: 64x32
        #pragma unroll
        for (int r = 0; r < 2; r++) {
            const float4 v = *reinterpret_cast<const float4*>(
                W + (size_t)(bn0 + lr + r * 32) * K + k0 + lc);
            Bs[lr + r * 32][lc + 0] = f2tf(v.x);
            Bs[lr + r * 32][lc + 1] = f2tf(v.y);
            Bs[lr + r * 32][lc + 2] = f2tf(v.z);
            Bs[lr + r * 32][lc + 3] = f2tf(v.w);
        }
        __syncthreads();

        #pragma unroll
        for (int ks = 0; ks < 4; ks++) {
            const int kk = ks * 8;
            uint32_t af[2][4], bf[4][2];
            #pragma unroll
            for (int mi = 0; mi < 2; mi++) {
                const int r = wm * 32 + mi * 16 + (lane >> 2);
                const int c = kk + (lane & 3);
                af[mi][0] = __float_as_uint(As[r][c]);
                af[mi][1] = __float_as_uint(As[r + 8][c]);
                af[mi][2] = __float_as_uint(As[r][c + 4]);
                af[mi][3] = __float_as_uint(As[r + 8][c + 4]);
            }
            #pragma unroll
            for (int ni = 0; ni < 4; ni++) {
                const int n = wn * 32 + ni * 8 + (lane >> 2);
                bf[ni][0] = __float_as_uint(Bs[n][kk + (lane & 3)]);
                bf[ni][1] = __float_as_uint(Bs[n][kk + (lane & 3) + 4]);
            }
            #pragma unroll
            for (int mi = 0; mi < 2; mi++)
                #pragma unroll
                for (int ni = 0; ni < 4; ni++)
                    mma_m16n8k8(acc[mi][ni], af[mi], bf[ni][0], bf[ni][1]);
        }
        __syncthreads();
    }

    // Epilogue
    #pragma unroll
    for (int mi = 0; mi < 2; mi++) {
        #pragma unroll
        for (int ni = 0; ni < 4; ni++) {
            const int r0 = bm0 + wm * 32 + mi * 16 + (lane >> 2);
            const int c0 = bn0 + wn * 32 + ni * 8 + ((lane & 3) << 1);
            #pragma unroll
            for (int e = 0; e < 4; e++) {
                const int r = r0 + (e >> 1) * 8;
                const int c = c0 + (e & 1);
                float v = acc[mi][ni][e] + bias[c];
                if (relu) v = resid[(size_t)r * N + c] + fmaxf(v, 0.f);
                C[(size_t)r * N + c] = v;
            }
        }
    }
}

// ---------------------------------------------------------------------------
// Attention: per (q-tile of 64, head). 128 threads (4 warps, 16 q-rows each).
// Flash-style online softmax; softmax-then-/32 quirk; O = q + A@V.
// Q fragments preloaded into registers (staged through Ks buffer).
// P (C-fragment layout) remapped to A-fragment layout via intra-quad shuffles.
//
// OUTPUT SCRAMBLE (reference quirk): O_heads[h, i, b] is written via plain
// row-major reshape to [2048, 1024]:
//   row' = h*128 + (i >> 4),   col' = (i & 15)*64 + b
// ---------------------------------------------------------------------------
#define AST 72   // 64 + 8 pad: all frag LDS patterns conflict-free; float4 ok

__global__ __launch_bounds__(128) void attn_kernel()
{
    const int qt = blockIdx.x;   // 0..31
    const int h  = blockIdx.y;   // 0..15
    __shared__ float Ks[64][AST];
    __shared__ float Vs[64][AST];

    const int tid  = threadIdx.x;
    const int lane = tid & 31;
    const int warp = tid >> 5;

    // Stage Q tile (tf32) through Ks, extract register fragments
    #pragma unroll
    for (int i = 0; i < 8; i++) {
        const int idx = tid + i * 128;
        const int r = idx >> 4;
        const int c = (idx & 15) << 2;
        const float4 v = *reinterpret_cast<const float4*>(
            g_q + (size_t)(qt * 64 + r) * DV + h * HD + c);
        Ks[r][c + 0] = f2tf(v.x);
        Ks[r][c + 1] = f2tf(v.y);
        Ks[r][c + 2] = f2tf(v.z);
        Ks[r][c + 3] = f2tf(v.w);
    }
    __syncthreads();

    uint32_t qf[8][4];
    #pragma unroll
    for (int ks = 0; ks < 8; ks++) {
        const int r = warp * 16 + (lane >> 2);
        const int c = ks * 8 + (lane & 3);
        qf[ks][0] = __float_as_uint(Ks[r][c]);
        qf[ks][1] = __float_as_uint(Ks[r + 8][c]);
        qf[ks][2] = __float_as_uint(Ks[r][c + 4]);
        qf[ks][3] = __float_as_uint(Ks[r + 8][c + 4]);
    }
    __syncthreads();

    float o[8][4];
    #pragma unroll
    for (int nd = 0; nd < 8; nd++)
        #pragma unroll
        for (int e = 0; e < 4; e++) o[nd][e] = 0.f;
    float m0 = -1e30f, m1 = -1e30f, l0 = 0.f, l1 = 0.f;

    for (int kt = 0; kt < 32; kt++) {
        // Load K, V tiles (64x64 each) for this head
        #pragma unroll
        for (int i = 0; i < 8; i++) {
            const int idx = tid + i * 128;
            const int r = idx >> 4;
            const int c = (idx & 15) << 2;
            const size_t off = (size_t)(kt * 64 + r) * DV + h * HD + c;
            const float4 kv = *reinterpret_cast<const float4*>(g_k + off);
            Ks[r][c + 0] = f2tf(kv.x);
            Ks[r][c + 1] = f2tf(kv.y);
            Ks[r][c + 2] = f2tf(kv.z);
            Ks[r][c + 3] = f2tf(kv.w);
            const float4 vv = *reinterpret_cast<const float4*>(g_v + off);
            Vs[r][c + 0] = f2tf(vv.x);
            Vs[r][c + 1] = f2tf(vv.y);
            Vs[r][c + 2] = f2tf(vv.z);
            Vs[r][c + 3] = f2tf(vv.w);
        }
        __syncthreads();

        // S = Q K^T   (16 rows x 64 cols per warp)
        float s[8][4];
        #pragma unroll
        for (int ni = 0; ni < 8; ni++)
            #pragma unroll
            for (int e = 0; e < 4; e++) s[ni][e] = 0.f;
        #pragma unroll
        for (int ni = 0; ni < 8; ni++) {
            const int n = ni * 8 + (lane >> 2);
            #pragma unroll
            for (int ks = 0; ks < 8; ks++) {
                const uint32_t b0 = __float_as_uint(Ks[n][ks * 8 + (lane & 3)]);
                const uint32_t b1 = __float_as_uint(Ks[n][ks * 8 + (lane & 3) + 4]);
                mma_m16n8k8(s[ni], qf[ks], b0, b1);
            }
        }

        // Online softmax (rows: lane>>2 and lane>>2 + 8)
        float mx0 = -1e30f, mx1 = -1e30f;
        #pragma unroll
        for (int ni = 0; ni < 8; ni++) {
            mx0 = fmaxf(mx0, fmaxf(s[ni][0], s[ni][1]));
            mx1 = fmaxf(mx1, fmaxf(s[ni][2], s[ni][3]));
        }
        mx0 = fmaxf(mx0, __shfl_xor_sync(0xffffffffu, mx0, 1));
        mx0 = fmaxf(mx0, __shfl_xor_sync(0xffffffffu, mx0, 2));
        mx1 = fmaxf(mx1, __shfl_xor_sync(0xffffffffu, mx1, 1));
        mx1 = fmaxf(mx1, __shfl_xor_sync(0xffffffffu, mx1, 2));
        const float mn0 = fmaxf(m0, mx0);
        const float mn1 = fmaxf(m1, mx1);
        const float a0 = __expf(m0 - mn0);
        const float a1 = __expf(m1 - mn1);
        float rs0 = 0.f, rs1 = 0.f;
        #pragma unroll
        for (int ni = 0; ni < 8; ni++) {
            s[ni][0] = __expf(s[ni][0] - mn0);
            s[ni][1] = __expf(s[ni][1] - mn0);
            s[ni][2] = __expf(s[ni][2] - mn1);
            s[ni][3] = __expf(s[ni][3] - mn1);
            rs0 += s[ni][0] + s[ni][1];
            rs1 += s[ni][2] + s[ni][3];
        }
        rs0 += __shfl_xor_sync(0xffffffffu, rs0, 1);
        rs0 += __shfl_xor_sync(0xffffffffu, rs0, 2);
        rs1 += __shfl_xor_sync(0xffffffffu, rs1, 1);
        rs1 += __shfl_xor_sync(0xffffffffu, rs1, 2);
        l0 = l0 * a0 + rs0;
        l1 = l1 * a1 + rs1;
        m0 = mn0;
        m1 = mn1;
        #pragma unroll
        for (int nd = 0; nd < 8; nd++) {
            o[nd][0] *= a0;
            o[nd][1] *= a0;
            o[nd][2] *= a1;
            o[nd][3] *= a1;
        }

        // O += P @ V ; remap P C-fragments -> A-fragments via quad shuffles
        #pragma unroll
        for (int kv = 0; kv < 8; kv++) {
            const int t = lane & 3;
            const int src0 = (lane & ~3) | (t >> 1);
            const int src2 = src0 + 2;
            const float c0 = __shfl_sync(0xffffffffu, s[kv][0], src0);
            const float c1 = __shfl_sync(0xffffffffu, s[kv][1], src0);
            const float c2 = __shfl_sync(0xffffffffu, s[kv][2], src0);
            const float c3 = __shfl_sync(0xffffffffu, s[kv][3], src0);
            const float d0 = __shfl_sync(0xffffffffu, s[kv][0], src2);
            const float d1 = __shfl_sync(0xffffffffu, s[kv][1], src2);
            const float d2 = __shfl_sync(0xffffffffu, s[kv][2], src2);
            const float d3 = __shfl_sync(0xffffffffu, s[kv][3], src2);
            const bool odd = t & 1;
            uint32_t pa[4];
            pa[0] = __float_as_uint(f2tf(odd ? c1 : c0));
            pa[1] = __float_as_uint(f2tf(odd ? c3 : c2));
            pa[2] = __float_as_uint(f2tf(odd ? d1 : d0));
            pa[3] = __float_as_uint(f2tf(odd ? d3 : d2));
            #pragma unroll
            for (int nd = 0; nd < 8; nd++) {
                const uint32_t b0 =
                    __float_as_uint(Vs[kv * 8 + (lane & 3)][nd * 8 + (lane >> 2)]);
                const uint32_t b1 =
                    __float_as_uint(Vs[kv * 8 + (lane & 3) + 4][nd * 8 + (lane >> 2)]);
                mma_m16n8k8(o[nd], pa, b0, b1);
            }
        }
        __syncthreads();
    }

    // Epilogue with the reference's reshape scramble:
    //   O_heads[h, i, b] -> out[h*128 + (i>>4)][ (i&15)*64 + b ]
    // Warp's two fragment rows i0 = qt*64+warp*16+g and i1 = i0+8 share the
    // same scrambled row (i>>4 identical) but land in different column blocks.
    const float inv0 = 1.f / (l0 * 32.f);
    const float inv1 = 1.f / (l1 * 32.f);
    const int g = lane >> 2;
    const int i0 = qt * 64 + warp * 16 + g;   // q row (frag rows 0,1)
    const int i1 = i0 + 8;                    // q row (frag rows 2,3)
    const int rp = h * 128 + qt * 4 + warp;   // scrambled row (same for both)
    #pragma unroll
    for (int nd = 0; nd < 8; nd++) {
        const int b = nd * 8 + ((lane & 3) << 1);   // in-head dim 0..62
        const int c0 = g * 64 + b;                  // i0 & 15 == g
        const int c1 = (g + 8) * 64 + b;            // i1 & 15 == g+8
        const size_t qi0 = (size_t)i0 * DV + h * HD + b;
        const size_t qi1 = (size_t)i1 * DV + h * HD + b;
        const size_t o0  = (size_t)rp * DV + c0;
        const size_t o1  = (size_t)rp * DV + c1;
        g_attn[o0]     = g_q[qi0]     + o[nd][0] * inv0;
        g_attn[o0 + 1] = g_q[qi0 + 1] + o[nd][1] * inv0;
        g_attn[o1]     = g_q[qi1]     + o[nd][2] * inv1;
        g_attn[o1 + 1] = g_q[qi1 + 1] + o[nd][3] * inv1;
    }
}

// ---------------------------------------------------------------------------
extern "C" void kernel_launch(void* const* d_in, const int* in_sizes, int n_in,
                              void* d_out, int out_size)
{
    const float* Q  = (const float*)d_in[0];
    const float* K  = (const float*)d_in[1];
    const float* Wq = (const float*)d_in[2];
    const float* bq = (const float*)d_in[3];
    const float* Wk = (const float*)d_in[4];
    const float* bk = (const float*)d_in[5];
    const float* Wv = (const float*)d_in[6];
    const float* bv = (const float*)d_in[7];
    const float* Wo = (const float*)d_in[8];
    const float* bo = (const float*)d_in[9];
    float* out = (float*)d_out;

    float *pq, *pk, *pv, *pa;
    cudaGetSymbolAddress((void**)&pq, g_q);
    cudaGetSymbolAddress((void**)&pk, g_k);
    cudaGetSymbolAddress((void**)&pv, g_v);
    cudaGetSymbolAddress((void**)&pa, g_attn);

    const dim3 gg(DV / BN, M_Q / BM);   // (16, 16)

    gemm_tf32<<<gg, 256>>>(Q, Wq, bq, pq, nullptr, M_Q, DV, DV, 0);
    gemm_tf32<<<gg, 256>>>(K, Wk, bk, pk, nullptr, M_Q, DV, DV, 0);
    gemm_tf32<<<gg, 256>>>(K, Wv, bv, pv, nullptr, M_Q, DV, DV, 0);
    attn_kernel<<<dim3(M_Q / 64, NH), 128>>>();
    gemm_tf32<<<gg, 256>>>(pa, Wo, bo, out, pa, M_Q, DV, DV, 1);
}

// round 3
// speedup vs baseline: 1.6058x; 1.6058x over previous
#include <cuda_runtime.h>
#include <cuda_bf16.h>
#include <cstdint>

// Problem constants
#define M_Q 2048          // rows of Q (and K)
#define DV  1024          // model dim
#define NH  16            // number of heads (DIM_SPLIT)
#define HD  64            // head dim

// Scratch (device globals: allocation-free)
__device__ float g_q[M_Q * DV];                 // fp32 q (residual)
__device__ float g_attn[M_Q * DV];              // attention output (scrambled)
__device__ __nv_bfloat16 g_qh[M_Q * DV];        // bf16 q for attention
__device__ __nv_bfloat16 g_kh[M_Q * DV];        // bf16 k
__device__ __nv_bfloat16 g_vh[M_Q * DV];        // bf16 v

__device__ __forceinline__ float f2tf(float x) {
    uint32_t r;
    asm("cvt.rna.tf32.f32 %0, %1;" : "=r"(r) : "f"(x));
    return __uint_as_float(r);
}

__device__ __forceinline__ void mma_m16n8k8(float (&d)[4],
                                            const uint32_t (&a)[4],
                                            uint32_t b0, uint32_t b1) {
    asm volatile(
        "mma.sync.aligned.m16n8k8.row.col.f32.tf32.tf32.f32 "
        "{%0,%1,%2,%3}, {%4,%5,%6,%7}, {%8,%9}, {%0,%1,%2,%3};\n"
        : "+f"(d[0]), "+f"(d[1]), "+f"(d[2]), "+f"(d[3])
        : "r"(a[0]), "r"(a[1]), "r"(a[2]), "r"(a[3]), "r"(b0), "r"(b1));
}

__device__ __forceinline__ void mma_bf16(float (&d)[4],
                                         const uint32_t (&a)[4],
                                         uint32_t b0, uint32_t b1) {
    asm volatile(
        "mma.sync.aligned.m16n8k16.row.col.f32.bf16.bf16.f32 "
        "{%0,%1,%2,%3}, {%4,%5,%6,%7}, {%8,%9}, {%0,%1,%2,%3};\n"
        : "+f"(d[0]), "+f"(d[1]), "+f"(d[2]), "+f"(d[3])
        : "r"(a[0]), "r"(a[1]), "r"(a[2]), "r"(a[3]), "r"(b0), "r"(b1));
}

__device__ __forceinline__ void ldsm4(uint32_t& r0, uint32_t& r1,
                                      uint32_t& r2, uint32_t& r3, uint32_t addr) {
    asm volatile("ldmatrix.sync.aligned.m8n8.x4.shared.b16 {%0,%1,%2,%3}, [%4];\n"
                 : "=r"(r0), "=r"(r1), "=r"(r2), "=r"(r3) : "r"(addr));
}
__device__ __forceinline__ void ldsm4t(uint32_t& r0, uint32_t& r1,
                                       uint32_t& r2, uint32_t& r3, uint32_t addr) {
    asm volatile("ldmatrix.sync.aligned.m8n8.x4.trans.shared.b16 {%0,%1,%2,%3}, [%4];\n"
                 : "=r"(r0), "=r"(r1), "=r"(r2), "=r"(r3) : "r"(addr));
}

__device__ __forceinline__ uint32_t packbf(float lo, float hi) {
    uint32_t r;
    asm("cvt.rn.bf16x2.f32 %0, %1, %2;" : "=r"(r) : "f"(hi), "f"(lo));
    return r;
}

// ---------------------------------------------------------------------------
// GEMM: C = epilogue(A[M,K] @ W[N,K]^T + bias[N]); tf32 path.
// Cf (fp32) and/or Ch (bf16) outputs; relu==1 adds resid + relu.
// ---------------------------------------------------------------------------
#define BM 128
#define BN 64
#define BK 32
#define LDA 36

__global__ __launch_bounds__(256) void gemm_tf32(
    const float* __restrict__ A, const float* __restrict__ W,
    const float* __restrict__ bias, float* __restrict__ Cf,
    __nv_bfloat16* __restrict__ Ch,
    const float* __restrict__ resid, int M, int N, int K, int relu)
{
    __shared__ float As[BM][LDA];
    __shared__ float Bs[BN][LDA];

    const int tid  = threadIdx.x;
    const int lane = tid & 31;
    const int warp = tid >> 5;
    const int wm = warp >> 1;
    const int wn = warp & 1;
    const int bm0 = blockIdx.y * BM;
    const int bn0 = blockIdx.x * BN;

    float acc[2][4][4];
    #pragma unroll
    for (int mi = 0; mi < 2; mi++)
        #pragma unroll
        for (int ni = 0; ni < 4; ni++)
            #pragma unroll
            for (int e = 0; e < 4; e++) acc[mi][ni][e] = 0.f;

    const int lr = tid >> 3;
    const int lc = (tid & 7) << 2;

    for (int k0 = 0; k0 < K; k0 += BK) {
        #pragma unroll
        for (int r = 0; r < 4; r++) {
            const float4 v = *reinterpret_cast<const float4*>(
                A + (size_t)(bm0 + lr + r * 32) * K + k0 + lc);
            As[lr + r * 32][lc + 0] = f2tf(v.x);
            As[lr + r * 32][lc + 1] = f2tf(v.y);
            As[lr + r * 32][lc + 2] = f2tf(v.z);
            As[lr + r * 32][lc + 3] = f2tf(v.w);
        }
        #pragma unroll
        for (int r = 0; r < 2; r++) {
            const float4 v = *reinterpret_cast<const float4*>(
                W + (size_t)(bn0 + lr + r * 32) * K + k0 + lc);
            Bs[lr + r * 32][lc + 0] = f2tf(v.x);
            Bs[lr + r * 32][lc + 1] = f2tf(v.y);
            Bs[lr + r * 32][lc + 2] = f2tf(v.z);
            Bs[lr + r * 32][lc + 3] = f2tf(v.w);
        }
        __syncthreads();

        #pragma unroll
        for (int ks = 0; ks < 4; ks++) {
            const int kk = ks * 8;
            uint32_t af[2][4], bf[4][2];
            #pragma unroll
            for (int mi = 0; mi < 2; mi++) {
                const int r = wm * 32 + mi * 16 + (lane >> 2);
                const int c = kk + (lane & 3);
                af[mi][0] = __float_as_uint(As[r][c]);
                af[mi][1] = __float_as_uint(As[r + 8][c]);
                af[mi][2] = __float_as_uint(As[r][c + 4]);
                af[mi][3] = __float_as_uint(As[r + 8][c + 4]);
            }
            #pragma unroll
            for (int ni = 0; ni < 4; ni++) {
                const int n = wn * 32 + ni * 8 + (lane >> 2);
                bf[ni][0] = __float_as_uint(Bs[n][kk + (lane & 3)]);
                bf[ni][1] = __float_as_uint(Bs[n][kk + (lane & 3) + 4]);
            }
            #pragma unroll
            for (int mi = 0; mi < 2; mi++)
                #pragma unroll
                for (int ni = 0; ni < 4; ni++)
                    mma_m16n8k8(acc[mi][ni], af[mi], bf[ni][0], bf[ni][1]);
        }
        __syncthreads();
    }

    #pragma unroll
    for (int mi = 0; mi < 2; mi++) {
        #pragma unroll
        for (int ni = 0; ni < 4; ni++) {
            const int r0 = bm0 + wm * 32 + mi * 16 + (lane >> 2);
            const int c0 = bn0 + wn * 32 + ni * 8 + ((lane & 3) << 1);
            #pragma unroll
            for (int e = 0; e < 4; e++) {
                const int r = r0 + (e >> 1) * 8;
                const int c = c0 + (e & 1);
                float v = acc[mi][ni][e] + bias[c];
                if (relu) v = resid[(size_t)r * N + c] + fmaxf(v, 0.f);
                if (Cf) Cf[(size_t)r * N + c] = v;
                if (Ch) Ch[(size_t)r * N + c] = __float2bfloat16(v);
            }
        }
    }
}

// ---------------------------------------------------------------------------
// Attention (bf16 tensor cores, flash-style):
// block = 256 threads (8 warps), 128 q-rows/block, one head per block.y.
// K/V tiles 64x64 bf16, double-buffered via cp.async.
// Fragments via ldmatrix; P(C-frag) -> A-frag with register bf16x2 packs.
//
// Output scramble (reference reshape quirk):
//   O_heads[h, i, b] -> out[h*128 + (i>>4)][(i&15)*64 + b]
// ---------------------------------------------------------------------------
#define KSTR 72                  // padded row stride (halfs); 144B, 16B-aligned
#define TBUF (64 * KSTR)         // halfs per K or V buffer

__device__ __forceinline__ void issue_kv_tile(uint32_t smbase, int buf, int kt,
                                              int h, int tid) {
    const size_t gro = (size_t)kt * 64 * DV + (size_t)h * HD;
    #pragma unroll
    for (int i = 0; i < 4; i++) {
        const int c = tid + i * 256;             // 0..1023
        const int r = (c >> 3) & 63;
        const int ch = c & 7;
        const bool isK = c < 512;
        const __nv_bfloat16* src =
            (isK ? g_kh : g_vh) + gro + (size_t)r * DV + ch * 8;
        const uint32_t dst =
            smbase + ((buf * 2 + (isK ? 0 : 1)) * TBUF + r * KSTR + ch * 8) * 2;
        asm volatile("cp.async.cg.shared.global [%0], [%1], 16;\n"
                     :: "r"(dst), "l"(src));
    }
    asm volatile("cp.async.commit_group;\n");
}

__global__ __launch_bounds__(256) void attn_kernel()
{
    __shared__ __align__(16) __nv_bfloat16 sm[4 * TBUF];   // K0 V0 K1 V1

    const int h  = blockIdx.y;
    const int q0 = blockIdx.x * 128;
    const int tid  = threadIdx.x;
    const int lane = tid & 31;
    const int warp = tid >> 5;
    const uint32_t smbase = (uint32_t)__cvta_generic_to_shared(sm);

    // ---- Stage Q tile [128][64] into smem (reusing KV area), extract frags
    {
        const __nv_bfloat16* qsrc = g_qh + (size_t)q0 * DV + (size_t)h * HD;
        #pragma unroll
        for (int i = 0; i < 4; i++) {
            const int c = tid + i * 256;         // 0..1023
            const int r = c >> 3, ch = c & 7;
            const uint4 v = *reinterpret_cast<const uint4*>(
                qsrc + (size_t)r * DV + ch * 8);
            *reinterpret_cast<uint4*>(&sm[r * KSTR + ch * 8]) = v;
        }
    }
    __syncthreads();

    uint32_t qf[4][4];
    {
        const int row  = warp * 16 + (lane & 7) + 8 * ((lane >> 3) & 1);
        const int colq = (lane >> 4) * 8;
        #pragma unroll
        for (int ks = 0; ks < 4; ks++) {
            const uint32_t a = smbase + (row * KSTR + ks * 16 + colq) * 2;
            ldsm4(qf[ks][0], qf[ks][1], qf[ks][2], qf[ks][3], a);
        }
    }
    __syncthreads();    // done reading Q area before cp.async overwrites it

    float o[8][4];
    #pragma unroll
    for (int nd = 0; nd < 8; nd++)
        #pragma unroll
        for (int e = 0; e < 4; e++) o[nd][e] = 0.f;
    float m0 = -1e30f, m1 = -1e30f, l0 = 0.f, l1 = 0.f;

    issue_kv_tile(smbase, 0, 0, h, tid);

    const int krow = (lane & 7) + 8 * (lane >> 4);
    const int kcol = 8 * ((lane >> 3) & 1);
    const int vrow = (lane & 7) + 8 * ((lane >> 3) & 1);
    const int vcol = 8 * (lane >> 4);

    for (int kt = 0; kt < 32; kt++) {
        const int b = kt & 1;
        asm volatile("cp.async.wait_group 0;\n");
        __syncthreads();
        if (kt < 31) issue_kv_tile(smbase, b ^ 1, kt + 1, h, tid);

        const uint32_t kbase = smbase + (2 * b) * TBUF * 2;
        const uint32_t vbase = smbase + (2 * b + 1) * TBUF * 2;

        // ---- S = Q K^T (16 x 64 per warp)
        float s[8][4];
        #pragma unroll
        for (int ni = 0; ni < 8; ni++)
            #pragma unroll
            for (int e = 0; e < 4; e++) s[ni][e] = 0.f;

        #pragma unroll
        for (int ks = 0; ks < 4; ks++) {
            #pragma unroll
            for (int p = 0; p < 4; p++) {
                uint32_t r0, r1, r2, r3;
                const uint32_t a =
                    kbase + ((16 * p + krow) * KSTR + ks * 16 + kcol) * 2;
                ldsm4(r0, r1, r2, r3, a);
                mma_bf16(s[2 * p],     qf[ks], r0, r1);
                mma_bf16(s[2 * p + 1], qf[ks], r2, r3);
            }
        }

        // ---- online softmax (rows lane>>2 and +8)
        float mx0 = -1e30f, mx1 = -1e30f;
        #pragma unroll
        for (int ni = 0; ni < 8; ni++) {
            mx0 = fmaxf(mx0, fmaxf(s[ni][0], s[ni][1]));
            mx1 = fmaxf(mx1, fmaxf(s[ni][2], s[ni][3]));
        }
        mx0 = fmaxf(mx0, __shfl_xor_sync(0xffffffffu, mx0, 1));
        mx0 = fmaxf(mx0, __shfl_xor_sync(0xffffffffu, mx0, 2));
        mx1 = fmaxf(mx1, __shfl_xor_sync(0xffffffffu, mx1, 1));
        mx1 = fmaxf(mx1, __shfl_xor_sync(0xffffffffu, mx1, 2));
        const float mn0 = fmaxf(m0, mx0);
        const float mn1 = fmaxf(m1, mx1);
        const float a0 = __expf(m0 - mn0);
        const float a1 = __expf(m1 - mn1);
        float rs0 = 0.f, rs1 = 0.f;
        #pragma unroll
        for (int ni = 0; ni < 8; ni++) {
            s[ni][0] = __expf(s[ni][0] - mn0);
            s[ni][1] = __expf(s[ni][1] - mn0);
            s[ni][2] = __expf(s[ni][2] - mn1);
            s[ni][3] = __expf(s[ni][3] - mn1);
            rs0 += s[ni][0] + s[ni][1];
            rs1 += s[ni][2] + s[ni][3];
        }
        rs0 += __shfl_xor_sync(0xffffffffu, rs0, 1);
        rs0 += __shfl_xor_sync(0xffffffffu, rs0, 2);
        rs1 += __shfl_xor_sync(0xffffffffu, rs1, 1);
        rs1 += __shfl_xor_sync(0xffffffffu, rs1, 2);
        l0 = l0 * a0 + rs0;
        l1 = l1 * a1 + rs1;
        m0 = mn0;
        m1 = mn1;
        #pragma unroll
        for (int nd = 0; nd < 8; nd++) {
            o[nd][0] *= a0;
            o[nd][1] *= a0;
            o[nd][2] *= a1;
            o[nd][3] *= a1;
        }

        // ---- O += P @ V ; P A-frags are pure register packs (no shuffles)
        #pragma unroll
        for (int kv = 0; kv < 4; kv++) {
            uint32_t pa[4];
            pa[0] = packbf(s[2 * kv][0], s[2 * kv][1]);
            pa[1] = packbf(s[2 * kv][2], s[2 * kv][3]);
            pa[2] = packbf(s[2 * kv + 1][0], s[2 * kv + 1][1]);
            pa[3] = packbf(s[2 * kv + 1][2], s[2 * kv + 1][3]);
            #pragma unroll
            for (int p = 0; p < 4; p++) {
                uint32_t r0, r1, r2, r3;
                const uint32_t a =
                    vbase + ((16 * kv + vrow) * KSTR + 16 * p + vcol) * 2;
                ldsm4t(r0, r1, r2, r3, a);
                mma_bf16(o[2 * p],     pa, r0, r1);
                mma_bf16(o[2 * p + 1], pa, r2, r3);
            }
        }
    }

    // ---- epilogue with reshape scramble
    const float inv0 = 1.f / (l0 * 32.f);
    const float inv1 = 1.f / (l1 * 32.f);
    const int g  = lane >> 2;
    const int i0 = q0 + warp * 16 + g;
    const int i1 = i0 + 8;
    const int rp = h * 128 + blockIdx.x * 8 + warp;
    #pragma unroll
    for (int nd = 0; nd < 8; nd++) {
        const int bcol = nd * 8 + ((lane & 3) << 1);
        const int c0 = g * 64 + bcol;
        const int c1 = (g + 8) * 64 + bcol;
        const size_t qi0 = (size_t)i0 * DV + h * HD + bcol;
        const size_t qi1 = (size_t)i1 * DV + h * HD + bcol;
        const size_t o0  = (size_t)rp * DV + c0;
        const size_t o1  = (size_t)rp * DV + c1;
        g_attn[o0]     = g_q[qi0]     + o[nd][0] * inv0;
        g_attn[o0 + 1] = g_q[qi0 + 1] + o[nd][1] * inv0;
        g_attn[o1]     = g_q[qi1]     + o[nd][2] * inv1;
        g_attn[o1 + 1] = g_q[qi1 + 1] + o[nd][3] * inv1;
    }
}

// ---------------------------------------------------------------------------
extern "C" void kernel_launch(void* const* d_in, const int* in_sizes, int n_in,
                              void* d_out, int out_size)
{
    const float* Q  = (const float*)d_in[0];
    const float* K  = (const float*)d_in[1];
    const float* Wq = (const float*)d_in[2];
    const float* bq = (const float*)d_in[3];
    const float* Wk = (const float*)d_in[4];
    const float* bk = (const float*)d_in[5];
    const float* Wv = (const float*)d_in[6];
    const float* bv = (const float*)d_in[7];
    const float* Wo = (const float*)d_in[8];
    const float* bo = (const float*)d_in[9];
    float* out = (float*)d_out;

    float *pq, *pa;
    __nv_bfloat16 *pqh, *pkh, *pvh;
    cudaGetSymbolAddress((void**)&pq,  g_q);
    cudaGetSymbolAddress((void**)&pa,  g_attn);
    cudaGetSymbolAddress((void**)&pqh, g_qh);
    cudaGetSymbolAddress((void**)&pkh, g_kh);
    cudaGetSymbolAddress((void**)&pvh, g_vh);

    const dim3 gg(DV / BN, M_Q / BM);   // (16, 16)

    gemm_tf32<<<gg, 256>>>(Q, Wq, bq, pq, pqh, nullptr, M_Q, DV, DV, 0);
    gemm_tf32<<<gg, 256>>>(K, Wk, bk, nullptr, pkh, nullptr, M_Q, DV, DV, 0);
    gemm_tf32<<<gg, 256>>>(K, Wv, bv, nullptr, pvh, nullptr, M_Q, DV, DV, 0);
    attn_kernel<<<dim3(M_Q / 128, NH), 256>>>();
    gemm_tf32<<<gg, 256>>>(pa, Wo, bo, out, nullptr, pa, M_Q, DV, DV, 1);
}

// round 4
// speedup vs baseline: 1.8119x; 1.1283x over previous
#include <cuda_runtime.h>
#include <cuda_bf16.h>
#include <cstdint>

// Problem constants
#define M_Q 2048
#define DV  1024
#define NH  16
#define HD  64

// Scratch (device globals: allocation-free)
__device__ float g_q[M_Q * DV];                 // fp32 q (residual for attn)
__device__ float g_attn[M_Q * DV];              // attention output (scrambled, fp32)
__device__ float g_attnr[M_Q * DV];             // tf32-rounded copy of g_attn
__device__ __nv_bfloat16 g_qh[M_Q * DV];
__device__ __nv_bfloat16 g_kh[M_Q * DV];
__device__ __nv_bfloat16 g_vh[M_Q * DV];
// tf32-pre-rounded inputs
__device__ float g_qr[M_Q * DV];
__device__ float g_kr[M_Q * DV];
__device__ float g_wq[DV * DV];
__device__ float g_wk[DV * DV];
__device__ float g_wv[DV * DV];
__device__ float g_wo[DV * DV];

__device__ __forceinline__ float f2tf(float x) {
    uint32_t r;
    asm("cvt.rna.tf32.f32 %0, %1;" : "=r"(r) : "f"(x));
    return __uint_as_float(r);
}

__device__ __forceinline__ void mma_m16n8k8(float (&d)[4],
                                            const uint32_t (&a)[4],
                                            uint32_t b0, uint32_t b1) {
    asm volatile(
        "mma.sync.aligned.m16n8k8.row.col.f32.tf32.tf32.f32 "
        "{%0,%1,%2,%3}, {%4,%5,%6,%7}, {%8,%9}, {%0,%1,%2,%3};\n"
        : "+f"(d[0]), "+f"(d[1]), "+f"(d[2]), "+f"(d[3])
        : "r"(a[0]), "r"(a[1]), "r"(a[2]), "r"(a[3]), "r"(b0), "r"(b1));
}

__device__ __forceinline__ void mma_bf16(float (&d)[4],
                                         const uint32_t (&a)[4],
                                         uint32_t b0, uint32_t b1) {
    asm volatile(
        "mma.sync.aligned.m16n8k16.row.col.f32.bf16.bf16.f32 "
        "{%0,%1,%2,%3}, {%4,%5,%6,%7}, {%8,%9}, {%0,%1,%2,%3};\n"
        : "+f"(d[0]), "+f"(d[1]), "+f"(d[2]), "+f"(d[3])
        : "r"(a[0]), "r"(a[1]), "r"(a[2]), "r"(a[3]), "r"(b0), "r"(b1));
}

__device__ __forceinline__ void ldsm4(uint32_t& r0, uint32_t& r1,
                                      uint32_t& r2, uint32_t& r3, uint32_t addr) {
    asm volatile("ldmatrix.sync.aligned.m8n8.x4.shared.b16 {%0,%1,%2,%3}, [%4];\n"
                 : "=r"(r0), "=r"(r1), "=r"(r2), "=r"(r3) : "r"(addr));
}
__device__ __forceinline__ void ldsm4t(uint32_t& r0, uint32_t& r1,
                                       uint32_t& r2, uint32_t& r3, uint32_t addr) {
    asm volatile("ldmatrix.sync.aligned.m8n8.x4.trans.shared.b16 {%0,%1,%2,%3}, [%4];\n"
                 : "=r"(r0), "=r"(r1), "=r"(r2), "=r"(r3) : "r"(addr));
}

__device__ __forceinline__ uint32_t packbf(float lo, float hi) {
    uint32_t r;
    asm("cvt.rn.bf16x2.f32 %0, %1, %2;" : "=r"(r) : "f"(hi), "f"(lo));
    return r;
}

// ---------------------------------------------------------------------------
// Pre-round pass: copy inputs with tf32 RN rounding into device scratch.
// Segments (float4 units): Q 512K | K 512K | Wq 256K | Wk 256K | Wv 256K | Wo 256K
// ---------------------------------------------------------------------------
__global__ __launch_bounds__(256) void round_tf32(
    const float4* __restrict__ Q, const float4* __restrict__ K,
    const float4* __restrict__ Wq, const float4* __restrict__ Wk,
    const float4* __restrict__ Wv, const float4* __restrict__ Wo)
{
    const int i = blockIdx.x * 256 + threadIdx.x;   // 0 .. 2M-1
    const float4* src;
    float4* dst;
    int off;
    if (i < 524288)        { src = Q;  dst = (float4*)g_qr; off = i; }
    else if (i < 1048576)  { src = K;  dst = (float4*)g_kr; off = i - 1048576 + 524288; }
    else if (i < 1310720)  { src = Wq; dst = (float4*)g_wq; off = i - 1048576; }
    else if (i < 1572864)  { src = Wk; dst = (float4*)g_wk; off = i - 1310720; }
    else if (i < 1835008)  { src = Wv; dst = (float4*)g_wv; off = i - 1572864; }
    else                   { src = Wo; dst = (float4*)g_wo; off = i - 1835008; }
    float4 v = src[off];
    v.x = f2tf(v.x); v.y = f2tf(v.y); v.z = f2tf(v.z); v.w = f2tf(v.w);
    dst[off] = v;
}

// ---------------------------------------------------------------------------
// GEMM v2: C = epilogue(A[2048,1024] @ W[1024,1024]^T + bias)
// BM=128 BN=128 BK=32; 256 threads, warps 2(m) x 4(n), warp tile 64x32.
// Double-buffered cp.async (72KB dynamic smem). Inputs pre-rounded to tf32.
// mode 0: Cf=fp32 out + Ch0=bf16 out          (q projection)
// mode 1: N=2048 fused; n<1024 -> W0/b0/Ch0, else W1/b1/Ch1   (k,v projection)
// mode 2: Cf = resid + relu(acc + bias)       (output projection)
// ---------------------------------------------------------------------------
#define GLDA 36
#define GSTG (128 * GLDA)          // floats per (A or B) tile
#define GSMEM (4 * GSTG * 4)       // bytes: 2 stages x (A+B)

__device__ __forceinline__ void gemm_issue(uint32_t smbase, int stage, int kb,
                                           const float* __restrict__ A,
                                           const float* __restrict__ W,
                                           int bm0, int ncol0, int tid)
{
    const uint32_t base = smbase + stage * (2 * GSTG * 4);
    #pragma unroll
    for (int i = 0; i < 4; i++) {
        const int id = tid + i * 256;          // 0..1023
        const int r  = id >> 3;
        const int c4 = (id & 7) << 2;
        const float* srcA = A + (size_t)(bm0 + r) * DV + kb * 32 + c4;
        const uint32_t dstA = base + (r * GLDA + c4) * 4;
        asm volatile("cp.async.cg.shared.global [%0], [%1], 16;\n"
                     :: "r"(dstA), "l"(srcA));
        const float* srcW = W + (size_t)(ncol0 + r) * DV + kb * 32 + c4;
        const uint32_t dstW = base + (GSTG + r * GLDA + c4) * 4;
        asm volatile("cp.async.cg.shared.global [%0], [%1], 16;\n"
                     :: "r"(dstW), "l"(srcW));
    }
    asm volatile("cp.async.commit_group;\n");
}

__global__ __launch_bounds__(256, 2) void gemm2(
    const float* __restrict__ A,
    const float* __restrict__ W0, const float* __restrict__ W1,
    const float* __restrict__ b0, const float* __restrict__ b1,
    float* __restrict__ Cf,
    __nv_bfloat16* __restrict__ Ch0, __nv_bfloat16* __restrict__ Ch1,
    const float* __restrict__ resid, int mode)
{
    extern __shared__ __align__(16) float smx[];
    const uint32_t smbase = (uint32_t)__cvta_generic_to_shared(smx);

    const int tid  = threadIdx.x;
    const int lane = tid & 31;
    const int warp = tid >> 5;
    const int wm = warp >> 2;          // 0..1
    const int wn = warp & 3;           // 0..3
    const int bm0 = blockIdx.y * 128;

    const float* W = W0;
    const float* bias = b0;
    __nv_bfloat16* Ch = Ch0;
    int ncol0 = blockIdx.x * 128;
    if (mode == 1 && ncol0 >= DV) { W = W1; bias = b1; Ch = Ch1; ncol0 -= DV; }

    float acc[4][4][4];
    #pragma unroll
    for (int mi = 0; mi < 4; mi++)
        #pragma unroll
        for (int ni = 0; ni < 4; ni++)
            #pragma unroll
            for (int e = 0; e < 4; e++) acc[mi][ni][e] = 0.f;

    gemm_issue(smbase, 0, 0, A, W, bm0, ncol0, tid);

    for (int kb = 0; kb < 32; kb++) {
        asm volatile("cp.async.wait_group 0;\n");
        __syncthreads();
        if (kb < 31) gemm_issue(smbase, (kb + 1) & 1, kb + 1, A, W, bm0, ncol0, tid);

        const float* As = smx + (kb & 1) * (2 * GSTG);
        const float* Bs = As + GSTG;

        #pragma unroll
        for (int ks = 0; ks < 4; ks++) {
            const int kk = ks * 8;
            uint32_t af[4][4], bf[4][2];
            #pragma unroll
            for (int mi = 0; mi < 4; mi++) {
                const int r = wm * 64 + mi * 16 + (lane >> 2);
                const int c = kk + (lane & 3);
                af[mi][0] = __float_as_uint(As[r * GLDA + c]);
                af[mi][1] = __float_as_uint(As[(r + 8) * GLDA + c]);
                af[mi][2] = __float_as_uint(As[r * GLDA + c + 4]);
                af[mi][3] = __float_as_uint(As[(r + 8) * GLDA + c + 4]);
            }
            #pragma unroll
            for (int ni = 0; ni < 4; ni++) {
                const int n = wn * 32 + ni * 8 + (lane >> 2);
                bf[ni][0] = __float_as_uint(Bs[n * GLDA + kk + (lane & 3)]);
                bf[ni][1] = __float_as_uint(Bs[n * GLDA + kk + (lane & 3) + 4]);
            }
            #pragma unroll
            for (int mi = 0; mi < 4; mi++)
                #pragma unroll
                for (int ni = 0; ni < 4; ni++)
                    mma_m16n8k8(acc[mi][ni], af[mi], bf[ni][0], bf[ni][1]);
        }
        __syncthreads();
    }

    // Epilogue
    #pragma unroll
    for (int mi = 0; mi < 4; mi++) {
        #pragma unroll
        for (int ni = 0; ni < 4; ni++) {
            const int r0 = bm0 + wm * 64 + mi * 16 + (lane >> 2);
            const int c0 = ncol0 + wn * 32 + ni * 8 + ((lane & 3) << 1);
            #pragma unroll
            for (int e = 0; e < 4; e++) {
                const int r = r0 + (e >> 1) * 8;
                const int c = c0 + (e & 1);
                float v = acc[mi][ni][e] + bias[c];
                if (mode == 2) {
                    v = resid[(size_t)r * DV + c] + fmaxf(v, 0.f);
                    Cf[(size_t)r * DV + c] = v;
                } else if (mode == 0) {
                    Cf[(size_t)r * DV + c] = v;
                    Ch[(size_t)r * DV + c] = __float2bfloat16(v);
                } else {
                    Ch[(size_t)r * DV + c] = __float2bfloat16(v);
                }
            }
        }
    }
}

// ---------------------------------------------------------------------------
// Attention (bf16 tensor cores, flash-style) — as R3, plus writes a
// tf32-rounded copy g_attnr for the output GEMM.
// Output scramble: O_heads[h, i, b] -> out[h*128 + (i>>4)][(i&15)*64 + b]
// ---------------------------------------------------------------------------
#define KSTR 72
#define TBUF (64 * KSTR)

__device__ __forceinline__ void issue_kv_tile(uint32_t smbase, int buf, int kt,
                                              int h, int tid) {
    const size_t gro = (size_t)kt * 64 * DV + (size_t)h * HD;
    #pragma unroll
    for (int i = 0; i < 4; i++) {
        const int c = tid + i * 256;
        const int r = (c >> 3) & 63;
        const int ch = c & 7;
        const bool isK = c < 512;
        const __nv_bfloat16* src =
            (isK ? g_kh : g_vh) + gro + (size_t)r * DV + ch * 8;
        const uint32_t dst =
            smbase + ((buf * 2 + (isK ? 0 : 1)) * TBUF + r * KSTR + ch * 8) * 2;
        asm volatile("cp.async.cg.shared.global [%0], [%1], 16;\n"
                     :: "r"(dst), "l"(src));
    }
    asm volatile("cp.async.commit_group;\n");
}

__global__ __launch_bounds__(256) void attn_kernel()
{
    __shared__ __align__(16) __nv_bfloat16 sm[4 * TBUF];

    const int h  = blockIdx.y;
    const int q0 = blockIdx.x * 128;
    const int tid  = threadIdx.x;
    const int lane = tid & 31;
    const int warp = tid >> 5;
    const uint32_t smbase = (uint32_t)__cvta_generic_to_shared(sm);

    {
        const __nv_bfloat16* qsrc = g_qh + (size_t)q0 * DV + (size_t)h * HD;
        #pragma unroll
        for (int i = 0; i < 4; i++) {
            const int c = tid + i * 256;
            const int r = c >> 3, ch = c & 7;
            const uint4 v = *reinterpret_cast<const uint4*>(
                qsrc + (size_t)r * DV + ch * 8);
            *reinterpret_cast<uint4*>(&sm[r * KSTR + ch * 8]) = v;
        }
    }
    __syncthreads();

    uint32_t qf[4][4];
    {
        const int row  = warp * 16 + (lane & 7) + 8 * ((lane >> 3) & 1);
        const int colq = (lane >> 4) * 8;
        #pragma unroll
        for (int ks = 0; ks < 4; ks++) {
            const uint32_t a = smbase + (row * KSTR + ks * 16 + colq) * 2;
            ldsm4(qf[ks][0], qf[ks][1], qf[ks][2], qf[ks][3], a);
        }
    }
    __syncthreads();

    float o[8][4];
    #pragma unroll
    for (int nd = 0; nd < 8; nd++)
        #pragma unroll
        for (int e = 0; e < 4; e++) o[nd][e] = 0.f;
    float m0 = -1e30f, m1 = -1e30f, l0 = 0.f, l1 = 0.f;

    issue_kv_tile(smbase, 0, 0, h, tid);

    const int krow = (lane & 7) + 8 * (lane >> 4);
    const int kcol = 8 * ((lane >> 3) & 1);
    const int vrow = (lane & 7) + 8 * ((lane >> 3) & 1);
    const int vcol = 8 * (lane >> 4);

    for (int kt = 0; kt < 32; kt++) {
        const int b = kt & 1;
        asm volatile("cp.async.wait_group 0;\n");
        __syncthreads();
        if (kt < 31) issue_kv_tile(smbase, b ^ 1, kt + 1, h, tid);

        const uint32_t kbase = smbase + (2 * b) * TBUF * 2;
        const uint32_t vbase = smbase + (2 * b + 1) * TBUF * 2;

        float s[8][4];
        #pragma unroll
        for (int ni = 0; ni < 8; ni++)
            #pragma unroll
            for (int e = 0; e < 4; e++) s[ni][e] = 0.f;

        #pragma unroll
        for (int ks = 0; ks < 4; ks++) {
            #pragma unroll
            for (int p = 0; p < 4; p++) {
                uint32_t r0, r1, r2, r3;
                const uint32_t a =
                    kbase + ((16 * p + krow) * KSTR + ks * 16 + kcol) * 2;
                ldsm4(r0, r1, r2, r3, a);
                mma_bf16(s[2 * p],     qf[ks], r0, r1);
                mma_bf16(s[2 * p + 1], qf[ks], r2, r3);
            }
        }

        float mx0 = -1e30f, mx1 = -1e30f;
        #pragma unroll
        for (int ni = 0; ni < 8; ni++) {
            mx0 = fmaxf(mx0, fmaxf(s[ni][0], s[ni][1]));
            mx1 = fmaxf(mx1, fmaxf(s[ni][2], s[ni][3]));
        }
        mx0 = fmaxf(mx0, __shfl_xor_sync(0xffffffffu, mx0, 1));
        mx0 = fmaxf(mx0, __shfl_xor_sync(0xffffffffu, mx0, 2));
        mx1 = fmaxf(mx1, __shfl_xor_sync(0xffffffffu, mx1, 1));
        mx1 = fmaxf(mx1, __shfl_xor_sync(0xffffffffu, mx1, 2));
        const float mn0 = fmaxf(m0, mx0);
        const float mn1 = fmaxf(m1, mx1);
        const float a0 = __expf(m0 - mn0);
        const float a1 = __expf(m1 - mn1);
        float rs0 = 0.f, rs1 = 0.f;
        #pragma unroll
        for (int ni = 0; ni < 8; ni++) {
            s[ni][0] = __expf(s[ni][0] - mn0);
            s[ni][1] = __expf(s[ni][1] - mn0);
            s[ni][2] = __expf(s[ni][2] - mn1);
            s[ni][3] = __expf(s[ni][3] - mn1);
            rs0 += s[ni][0] + s[ni][1];
            rs1 += s[ni][2] + s[ni][3];
        }
        rs0 += __shfl_xor_sync(0xffffffffu, rs0, 1);
        rs0 += __shfl_xor_sync(0xffffffffu, rs0, 2);
        rs1 += __shfl_xor_sync(0xffffffffu, rs1, 1);
        rs1 += __shfl_xor_sync(0xffffffffu, rs1, 2);
        l0 = l0 * a0 + rs0;
        l1 = l1 * a1 + rs1;
        m0 = mn0;
        m1 = mn1;
        #pragma unroll
        for (int nd = 0; nd < 8; nd++) {
            o[nd][0] *= a0;
            o[nd][1] *= a0;
            o[nd][2] *= a1;
            o[nd][3] *= a1;
        }

        #pragma unroll
        for (int kv = 0; kv < 4; kv++) {
            uint32_t pa[4];
            pa[0] = packbf(s[2 * kv][0], s[2 * kv][1]);
            pa[1] = packbf(s[2 * kv][2], s[2 * kv][3]);
            pa[2] = packbf(s[2 * kv + 1][0], s[2 * kv + 1][1]);
            pa[3] = packbf(s[2 * kv + 1][2], s[2 * kv + 1][3]);
            #pragma unroll
            for (int p = 0; p < 4; p++) {
                uint32_t r0, r1, r2, r3;
                const uint32_t a =
                    vbase + ((16 * kv + vrow) * KSTR + 16 * p + vcol) * 2;
                ldsm4t(r0, r1, r2, r3, a);
                mma_bf16(o[2 * p],     pa, r0, r1);
                mma_bf16(o[2 * p + 1], pa, r2, r3);
            }
        }
    }

    const float inv0 = 1.f / (l0 * 32.f);
    const float inv1 = 1.f / (l1 * 32.f);
    const int g  = lane >> 2;
    const int i0 = q0 + warp * 16 + g;
    const int i1 = i0 + 8;
    const int rp = h * 128 + blockIdx.x * 8 + warp;
    #pragma unroll
    for (int nd = 0; nd < 8; nd++) {
        const int bcol = nd * 8 + ((lane & 3) << 1);
        const int c0 = g * 64 + bcol;
        const int c1 = (g + 8) * 64 + bcol;
        const size_t qi0 = (size_t)i0 * DV + h * HD + bcol;
        const size_t qi1 = (size_t)i1 * DV + h * HD + bcol;
        const size_t o0  = (size_t)rp * DV + c0;
        const size_t o1  = (size_t)rp * DV + c1;
        const float v00 = g_q[qi0]     + o[nd][0] * inv0;
        const float v01 = g_q[qi0 + 1] + o[nd][1] * inv0;
        const float v10 = g_q[qi1]     + o[nd][2] * inv1;
        const float v11 = g_q[qi1 + 1] + o[nd][3] * inv1;
        g_attn[o0]      = v00;  g_attn[o0 + 1]  = v01;
        g_attn[o1]      = v10;  g_attn[o1 + 1]  = v11;
        g_attnr[o0]     = f2tf(v00);  g_attnr[o0 + 1] = f2tf(v01);
        g_attnr[o1]     = f2tf(v10);  g_attnr[o1 + 1] = f2tf(v11);
    }
}

// ---------------------------------------------------------------------------
extern "C" void kernel_launch(void* const* d_in, const int* in_sizes, int n_in,
                              void* d_out, int out_size)
{
    const float* Q  = (const float*)d_in[0];
    const float* K  = (const float*)d_in[1];
    const float* bq = (const float*)d_in[3];
    const float* bk = (const float*)d_in[5];
    const float* bv = (const float*)d_in[7];
    const float* bo = (const float*)d_in[9];
    float* out = (float*)d_out;

    float *pq, *pa, *par, *pqr, *pkr, *pwq, *pwk, *pwv, *pwo;
    __nv_bfloat16 *pqh, *pkh, *pvh;
    cudaGetSymbolAddress((void**)&pq,  g_q);
    cudaGetSymbolAddress((void**)&pa,  g_attn);
    cudaGetSymbolAddress((void**)&par, g_attnr);
    cudaGetSymbolAddress((void**)&pqr, g_qr);
    cudaGetSymbolAddress((void**)&pkr, g_kr);
    cudaGetSymbolAddress((void**)&pwq, g_wq);
    cudaGetSymbolAddress((void**)&pwk, g_wk);
    cudaGetSymbolAddress((void**)&pwv, g_wv);
    cudaGetSymbolAddress((void**)&pwo, g_wo);
    cudaGetSymbolAddress((void**)&pqh, g_qh);
    cudaGetSymbolAddress((void**)&pkh, g_kh);
    cudaGetSymbolAddress((void**)&pvh, g_vh);

    cudaFuncSetAttribute(gemm2, cudaFuncAttributeMaxDynamicSharedMemorySize,
                         GSMEM);

    round_tf32<<<8192, 256>>>((const float4*)Q, (const float4*)K,
                              (const float4*)d_in[2], (const float4*)d_in[4],
                              (const float4*)d_in[6], (const float4*)d_in[8]);
    // q projection: fp32 + bf16 outputs
    gemm2<<<dim3(8, 16), 256, GSMEM>>>(pqr, pwq, nullptr, bq, nullptr,
                                       pq, pqh, nullptr, nullptr, 0);
    // fused k,v projection: bf16 outputs
    gemm2<<<dim3(16, 16), 256, GSMEM>>>(pkr, pwk, pwv, bk, bv,
                                        nullptr, pkh, pvh, nullptr, 1);
    attn_kernel<<<dim3(M_Q / 128, NH), 256>>>();
    // output projection with relu + residual
    gemm2<<<dim3(8, 16), 256, GSMEM>>>(par, pwo, nullptr, bo, nullptr,
                                       out, nullptr, nullptr, pa, 2);
}

// round 5
// speedup vs baseline: 2.4274x; 1.3397x over previous
#include <cuda_runtime.h>
#include <cuda_bf16.h>
#include <cuda_fp16.h>
#include <cstdint>

#define M_Q 2048
#define DV  1024
#define NH  16
#define HD  64

// Scratch (device globals: allocation-free)
__device__ float g_q[M_Q * DV];                 // fp32 q (residual for attn)
__device__ float g_attn[M_Q * DV];              // attention output (scrambled, fp32)
__device__ __half g_attnh[M_Q * DV];            // fp16 copy for Wo GEMM
__device__ __nv_bfloat16 g_qh[M_Q * DV];        // bf16 activations for attention
__device__ __nv_bfloat16 g_kh[M_Q * DV];
__device__ __nv_bfloat16 g_vh[M_Q * DV];
// fp16 pre-converted GEMM inputs
__device__ __half g_qin[M_Q * DV];
__device__ __half g_kin[M_Q * DV];
__device__ __half g_wqh[DV * DV];
__device__ __half g_wkh[DV * DV];
__device__ __half g_wvh[DV * DV];
__device__ __half g_woh[DV * DV];

__device__ __forceinline__ void mma_f16(float (&d)[4],
                                        const uint32_t (&a)[4],
                                        uint32_t b0, uint32_t b1) {
    asm volatile(
        "mma.sync.aligned.m16n8k16.row.col.f32.f16.f16.f32 "
        "{%0,%1,%2,%3}, {%4,%5,%6,%7}, {%8,%9}, {%0,%1,%2,%3};\n"
        : "+f"(d[0]), "+f"(d[1]), "+f"(d[2]), "+f"(d[3])
        : "r"(a[0]), "r"(a[1]), "r"(a[2]), "r"(a[3]), "r"(b0), "r"(b1));
}

__device__ __forceinline__ void mma_bf16(float (&d)[4],
                                         const uint32_t (&a)[4],
                                         uint32_t b0, uint32_t b1) {
    asm volatile(
        "mma.sync.aligned.m16n8k16.row.col.f32.bf16.bf16.f32 "
        "{%0,%1,%2,%3}, {%4,%5,%6,%7}, {%8,%9}, {%0,%1,%2,%3};\n"
        : "+f"(d[0]), "+f"(d[1]), "+f"(d[2]), "+f"(d[3])
        : "r"(a[0]), "r"(a[1]), "r"(a[2]), "r"(a[3]), "r"(b0), "r"(b1));
}

__device__ __forceinline__ void ldsm4(uint32_t& r0, uint32_t& r1,
                                      uint32_t& r2, uint32_t& r3, uint32_t addr) {
    asm volatile("ldmatrix.sync.aligned.m8n8.x4.shared.b16 {%0,%1,%2,%3}, [%4];\n"
                 : "=r"(r0), "=r"(r1), "=r"(r2), "=r"(r3) : "r"(addr));
}
__device__ __forceinline__ void ldsm4t(uint32_t& r0, uint32_t& r1,
                                       uint32_t& r2, uint32_t& r3, uint32_t addr) {
    asm volatile("ldmatrix.sync.aligned.m8n8.x4.trans.shared.b16 {%0,%1,%2,%3}, [%4];\n"
                 : "=r"(r0), "=r"(r1), "=r"(r2), "=r"(r3) : "r"(addr));
}

__device__ __forceinline__ uint32_t packbf(float lo, float hi) {
    uint32_t r;
    asm("cvt.rn.bf16x2.f32 %0, %1, %2;" : "=r"(r) : "f"(hi), "f"(lo));
    return r;
}

// ---------------------------------------------------------------------------
// Pre-convert pass: fp32 -> fp16 copies of Q, K, Wq, Wk, Wv, Wo.
// Indexed in float4 units: Q 512K | K 512K | Wq..Wo 256K each.
// ---------------------------------------------------------------------------
__global__ __launch_bounds__(256) void conv_f16(
    const float4* __restrict__ Q, const float4* __restrict__ K,
    const float4* __restrict__ Wq, const float4* __restrict__ Wk,
    const float4* __restrict__ Wv, const float4* __restrict__ Wo)
{
    const int i = blockIdx.x * 256 + threadIdx.x;   // 0 .. 2M-1
    const float4* src;
    __half* dst;
    int off;
    if (i < 524288)        { src = Q;  dst = g_qin; off = i; }
    else if (i < 1048576)  { src = K;  dst = g_kin; off = i - 524288; }
    else if (i < 1310720)  { src = Wq; dst = g_wqh; off = i - 1048576; }
    else if (i < 1572864)  { src = Wk; dst = g_wkh; off = i - 1310720; }
    else if (i < 1835008)  { src = Wv; dst = g_wvh; off = i - 1572864; }
    else                   { src = Wo; dst = g_woh; off = i - 1835008; }
    const float4 v = src[off];
    __half2* d2 = reinterpret_cast<__half2*>(dst) + off * 2;
    d2[0] = __floats2half2_rn(v.x, v.y);
    d2[1] = __floats2half2_rn(v.z, v.w);
}

// ---------------------------------------------------------------------------
// GEMM v3 (fp16 tensor cores): C = epilogue(A[2048,1024] @ W[1024,1024]^T + b)
// BM=128 BN=128 BK=64; 256 threads, warps 2(m) x 4(n), warp tile 64x32.
// Double-buffered cp.async; ldmatrix fragment loads.
// mode 0: Cf=fp32 + Ch0=bf16            (q projection)
// mode 1: N=2048 fused; n<1024 -> W0/b0/Ch0 else W1/b1/Ch1   (k,v projection)
// mode 2: Cf = resid + relu(acc+bias)   (output projection)
// ---------------------------------------------------------------------------
#define LDH 72
#define HSTG (128 * LDH)               // halves per tile
#define STGB (2 * HSTG * 2)            // bytes per stage (A+B)
#define G3SMEM (2 * STGB)

__device__ __forceinline__ void gemm3_issue(uint32_t smbase, int stage, int kb,
                                            const __half* __restrict__ A,
                                            const __half* __restrict__ W,
                                            int bm0, int n0, int tid)
{
    const uint32_t base = smbase + stage * STGB;
    #pragma unroll
    for (int i = 0; i < 4; i++) {
        const int id = tid + i * 256;          // 0..1023
        const int r  = id >> 3;
        const int ch = (id & 7) << 3;          // 0..56 step 8
        const __half* srcA = A + (size_t)(bm0 + r) * DV + kb * 64 + ch;
        asm volatile("cp.async.cg.shared.global [%0], [%1], 16;\n"
                     :: "r"(base + (r * LDH + ch) * 2), "l"(srcA));
        const __half* srcW = W + (size_t)(n0 + r) * DV + kb * 64 + ch;
        asm volatile("cp.async.cg.shared.global [%0], [%1], 16;\n"
                     :: "r"(base + (HSTG + r * LDH + ch) * 2), "l"(srcW));
    }
    asm volatile("cp.async.commit_group;\n");
}

__global__ __launch_bounds__(256) void gemm3(
    const __half* __restrict__ A,
    const __half* __restrict__ W0, const __half* __restrict__ W1,
    const float* __restrict__ b0, const float* __restrict__ b1,
    float* __restrict__ Cf,
    __nv_bfloat16* __restrict__ Ch0, __nv_bfloat16* __restrict__ Ch1,
    const float* __restrict__ resid, int mode)
{
    extern __shared__ __align__(16) __half smh[];
    const uint32_t smbase = (uint32_t)__cvta_generic_to_shared(smh);

    const int tid  = threadIdx.x;
    const int lane = tid & 31;
    const int warp = tid >> 5;
    const int wm = warp >> 2;          // 0..1
    const int wn = warp & 3;           // 0..3
    const int bm0 = blockIdx.y * 128;

    const __half* W = W0;
    const float* bias = b0;
    __nv_bfloat16* Ch = Ch0;
    int ncol0 = blockIdx.x * 128;
    if (mode == 1 && ncol0 >= DV) { W = W1; bias = b1; Ch = Ch1; ncol0 -= DV; }

    float acc[4][4][4];
    #pragma unroll
    for (int mi = 0; mi < 4; mi++)
        #pragma unroll
        for (int ni = 0; ni < 4; ni++)
            #pragma unroll
            for (int e = 0; e < 4; e++) acc[mi][ni][e] = 0.f;

    gemm3_issue(smbase, 0, 0, A, W, bm0, ncol0, tid);

    // ldmatrix lane addressing
    const int arow = lane & 15;            // A: row within 16-row tile
    const int acol = (lane >> 4) << 3;     // A: 0 or 8 (k half)
    const int brow = (lane & 7) + 8 * (lane >> 4);   // B: row within 16-n blk
    const int bcol = ((lane >> 3) & 1) << 3;         // B: 0 or 8 (k half)

    for (int kb = 0; kb < 16; kb++) {
        asm volatile("cp.async.wait_group 0;\n");
        __syncthreads();
        if (kb < 15) gemm3_issue(smbase, (kb + 1) & 1, kb + 1, A, W, bm0, ncol0, tid);

        const uint32_t abase = smbase + (kb & 1) * STGB;
        const uint32_t bbase = abase + HSTG * 2;

        #pragma unroll
        for (int ks = 0; ks < 4; ks++) {
            uint32_t af[4][4];
            #pragma unroll
            for (int mi = 0; mi < 4; mi++) {
                const int r = wm * 64 + mi * 16 + arow;
                ldsm4(af[mi][0], af[mi][1], af[mi][2], af[mi][3],
                      abase + (r * LDH + ks * 16 + acol) * 2);
            }
            #pragma unroll
            for (int p = 0; p < 2; p++) {
                uint32_t r0, r1, r2, r3;
                const int n = wn * 32 + 16 * p + brow;
                ldsm4(r0, r1, r2, r3, bbase + (n * LDH + ks * 16 + bcol) * 2);
                #pragma unroll
                for (int mi = 0; mi < 4; mi++) {
                    mma_f16(acc[mi][2 * p],     af[mi], r0, r1);
                    mma_f16(acc[mi][2 * p + 1], af[mi], r2, r3);
                }
            }
        }
        __syncthreads();
    }

    // Epilogue
    #pragma unroll
    for (int mi = 0; mi < 4; mi++) {
        #pragma unroll
        for (int ni = 0; ni < 4; ni++) {
            const int r0 = bm0 + wm * 64 + mi * 16 + (lane >> 2);
            const int c0 = ncol0 + wn * 32 + ni * 8 + ((lane & 3) << 1);
            #pragma unroll
            for (int e = 0; e < 4; e++) {
                const int r = r0 + (e >> 1) * 8;
                const int c = c0 + (e & 1);
                float v = acc[mi][ni][e] + bias[c];
                if (mode == 2) {
                    v = resid[(size_t)r * DV + c] + fmaxf(v, 0.f);
                    Cf[(size_t)r * DV + c] = v;
                } else if (mode == 0) {
                    Cf[(size_t)r * DV + c] = v;
                    Ch[(size_t)r * DV + c] = __float2bfloat16(v);
                } else {
                    Ch[(size_t)r * DV + c] = __float2bfloat16(v);
                }
            }
        }
    }
}

// ---------------------------------------------------------------------------
// Attention (bf16 tensor cores, flash-style) — unchanged from R3/R4 except the
// epilogue now also writes an fp16 copy (g_attnh) for the Wo GEMM.
// Output scramble: O_heads[h, i, b] -> out[h*128 + (i>>4)][(i&15)*64 + b]
// ---------------------------------------------------------------------------
#define KSTR 72
#define TBUF (64 * KSTR)

__device__ __forceinline__ void issue_kv_tile(uint32_t smbase, int buf, int kt,
                                              int h, int tid) {
    const size_t gro = (size_t)kt * 64 * DV + (size_t)h * HD;
    #pragma unroll
    for (int i = 0; i < 4; i++) {
        const int c = tid + i * 256;
        const int r = (c >> 3) & 63;
        const int ch = c & 7;
        const bool isK = c < 512;
        const __nv_bfloat16* src =
            (isK ? g_kh : g_vh) + gro + (size_t)r * DV + ch * 8;
        const uint32_t dst =
            smbase + ((buf * 2 + (isK ? 0 : 1)) * TBUF + r * KSTR + ch * 8) * 2;
        asm volatile("cp.async.cg.shared.global [%0], [%1], 16;\n"
                     :: "r"(dst), "l"(src));
    }
    asm volatile("cp.async.commit_group;\n");
}

__global__ __launch_bounds__(256) void attn_kernel()
{
    __shared__ __align__(16) __nv_bfloat16 sm[4 * TBUF];

    const int h  = blockIdx.y;
    const int q0 = blockIdx.x * 128;
    const int tid  = threadIdx.x;
    const int lane = tid & 31;
    const int warp = tid >> 5;
    const uint32_t smbase = (uint32_t)__cvta_generic_to_shared(sm);

    {
        const __nv_bfloat16* qsrc = g_qh + (size_t)q0 * DV + (size_t)h * HD;
        #pragma unroll
        for (int i = 0; i < 4; i++) {
            const int c = tid + i * 256;
            const int r = c >> 3, ch = c & 7;
            const uint4 v = *reinterpret_cast<const uint4*>(
                qsrc + (size_t)r * DV + ch * 8);
            *reinterpret_cast<uint4*>(&sm[r * KSTR + ch * 8]) = v;
        }
    }
    __syncthreads();

    uint32_t qf[4][4];
    {
        const int row  = warp * 16 + (lane & 15);
        const int colq = (lane >> 4) * 8;
        #pragma unroll
        for (int ks = 0; ks < 4; ks++) {
            const uint32_t a = smbase + (row * KSTR + ks * 16 + colq) * 2;
            ldsm4(qf[ks][0], qf[ks][1], qf[ks][2], qf[ks][3], a);
        }
    }
    __syncthreads();

    float o[8][4];
    #pragma unroll
    for (int nd = 0; nd < 8; nd++)
        #pragma unroll
        for (int e = 0; e < 4; e++) o[nd][e] = 0.f;
    float m0 = -1e30f, m1 = -1e30f, l0 = 0.f, l1 = 0.f;

    issue_kv_tile(smbase, 0, 0, h, tid);

    const int krow = (lane & 7) + 8 * (lane >> 4);
    const int kcol = 8 * ((lane >> 3) & 1);
    const int vrow = (lane & 7) + 8 * ((lane >> 3) & 1);
    const int vcol = 8 * (lane >> 4);

    for (int kt = 0; kt < 32; kt++) {
        const int b = kt & 1;
        asm volatile("cp.async.wait_group 0;\n");
        __syncthreads();
        if (kt < 31) issue_kv_tile(smbase, b ^ 1, kt + 1, h, tid);

        const uint32_t kbase = smbase + (2 * b) * TBUF * 2;
        const uint32_t vbase = smbase + (2 * b + 1) * TBUF * 2;

        float s[8][4];
        #pragma unroll
        for (int ni = 0; ni < 8; ni++)
            #pragma unroll
            for (int e = 0; e < 4; e++) s[ni][e] = 0.f;

        #pragma unroll
        for (int ks = 0; ks < 4; ks++) {
            #pragma unroll
            for (int p = 0; p < 4; p++) {
                uint32_t r0, r1, r2, r3;
                const uint32_t a =
                    kbase + ((16 * p + krow) * KSTR + ks * 16 + kcol) * 2;
                ldsm4(r0, r1, r2, r3, a);
                mma_bf16(s[2 * p],     qf[ks], r0, r1);
                mma_bf16(s[2 * p + 1], qf[ks], r2, r3);
            }
        }

        float mx0 = -1e30f, mx1 = -1e30f;
        #pragma unroll
        for (int ni = 0; ni < 8; ni++) {
            mx0 = fmaxf(mx0, fmaxf(s[ni][0], s[ni][1]));
            mx1 = fmaxf(mx1, fmaxf(s[ni][2], s[ni][3]));
        }
        mx0 = fmaxf(mx0, __shfl_xor_sync(0xffffffffu, mx0, 1));
        mx0 = fmaxf(mx0, __shfl_xor_sync(0xffffffffu, mx0, 2));
        mx1 = fmaxf(mx1, __shfl_xor_sync(0xffffffffu, mx1, 1));
        mx1 = fmaxf(mx1, __shfl_xor_sync(0xffffffffu, mx1, 2));
        const float mn0 = fmaxf(m0, mx0);
        const float mn1 = fmaxf(m1, mx1);
        const float a0 = __expf(m0 - mn0);
        const float a1 = __expf(m1 - mn1);
        float rs0 = 0.f, rs1 = 0.f;
        #pragma unroll
        for (int ni = 0; ni < 8; ni++) {
            s[ni][0] = __expf(s[ni][0] - mn0);
            s[ni][1] = __expf(s[ni][1] - mn0);
            s[ni][2] = __expf(s[ni][2] - mn1);
            s[ni][3] = __expf(s[ni][3] - mn1);
            rs0 += s[ni][0] + s[ni][1];
            rs1 += s[ni][2] + s[ni][3];
        }
        rs0 += __shfl_xor_sync(0xffffffffu, rs0, 1);
        rs0 += __shfl_xor_sync(0xffffffffu, rs0, 2);
        rs1 += __shfl_xor_sync(0xffffffffu, rs1, 1);
        rs1 += __shfl_xor_sync(0xffffffffu, rs1, 2);
        l0 = l0 * a0 + rs0;
        l1 = l1 * a1 + rs1;
        m0 = mn0;
        m1 = mn1;
        #pragma unroll
        for (int nd = 0; nd < 8; nd++) {
            o[nd][0] *= a0;
            o[nd][1] *= a0;
            o[nd][2] *= a1;
            o[nd][3] *= a1;
        }

        #pragma unroll
        for (int kv = 0; kv < 4; kv++) {
            uint32_t pa[4];
            pa[0] = packbf(s[2 * kv][0], s[2 * kv][1]);
            pa[1] = packbf(s[2 * kv][2], s[2 * kv][3]);
            pa[2] = packbf(s[2 * kv + 1][0], s[2 * kv + 1][1]);
            pa[3] = packbf(s[2 * kv + 1][2], s[2 * kv + 1][3]);
            #pragma unroll
            for (int p = 0; p < 4; p++) {
                uint32_t r0, r1, r2, r3;
                const uint32_t a =
                    vbase + ((16 * kv + vrow) * KSTR + 16 * p + vcol) * 2;
                ldsm4t(r0, r1, r2, r3, a);
                mma_bf16(o[2 * p],     pa, r0, r1);
                mma_bf16(o[2 * p + 1], pa, r2, r3);
            }
        }
    }

    const float inv0 = 1.f / (l0 * 32.f);
    const float inv1 = 1.f / (l1 * 32.f);
    const int g  = lane >> 2;
    const int i0 = q0 + warp * 16 + g;
    const int i1 = i0 + 8;
    const int rp = h * 128 + blockIdx.x * 8 + warp;
    #pragma unroll
    for (int nd = 0; nd < 8; nd++) {
        const int bc = nd * 8 + ((lane & 3) << 1);
        const int c0 = g * 64 + bc;
        const int c1 = (g + 8) * 64 + bc;
        const size_t qi0 = (size_t)i0 * DV + h * HD + bc;
        const size_t qi1 = (size_t)i1 * DV + h * HD + bc;
        const size_t o0  = (size_t)rp * DV + c0;
        const size_t o1  = (size_t)rp * DV + c1;
        const float v00 = g_q[qi0]     + o[nd][0] * inv0;
        const float v01 = g_q[qi0 + 1] + o[nd][1] * inv0;
        const float v10 = g_q[qi1]     + o[nd][2] * inv1;
        const float v11 = g_q[qi1 + 1] + o[nd][3] * inv1;
        g_attn[o0]      = v00;  g_attn[o0 + 1]  = v01;
        g_attn[o1]      = v10;  g_attn[o1 + 1]  = v11;
        g_attnh[o0]     = __float2half(v00);
        g_attnh[o0 + 1] = __float2half(v01);
        g_attnh[o1]     = __float2half(v10);
        g_attnh[o1 + 1] = __float2half(v11);
    }
}

// ---------------------------------------------------------------------------
extern "C" void kernel_launch(void* const* d_in, const int* in_sizes, int n_in,
                              void* d_out, int out_size)
{
    const float* Q  = (const float*)d_in[0];
    const float* K  = (const float*)d_in[1];
    const float* bq = (const float*)d_in[3];
    const float* bk = (const float*)d_in[5];
    const float* bv = (const float*)d_in[7];
    const float* bo = (const float*)d_in[9];
    float* out = (float*)d_out;

    float *pq, *pa;
    __half *pqi, *pki, *pwq, *pwk, *pwv, *pwo, *pah;
    __nv_bfloat16 *pqh, *pkh, *pvh;
    cudaGetSymbolAddress((void**)&pq,  g_q);
    cudaGetSymbolAddress((void**)&pa,  g_attn);
    cudaGetSymbolAddress((void**)&pah, g_attnh);
    cudaGetSymbolAddress((void**)&pqi, g_qin);
    cudaGetSymbolAddress((void**)&pki, g_kin);
    cudaGetSymbolAddress((void**)&pwq, g_wqh);
    cudaGetSymbolAddress((void**)&pwk, g_wkh);
    cudaGetSymbolAddress((void**)&pwv, g_wvh);
    cudaGetSymbolAddress((void**)&pwo, g_woh);
    cudaGetSymbolAddress((void**)&pqh, g_qh);
    cudaGetSymbolAddress((void**)&pkh, g_kh);
    cudaGetSymbolAddress((void**)&pvh, g_vh);

    cudaFuncSetAttribute(gemm3, cudaFuncAttributeMaxDynamicSharedMemorySize,
                         G3SMEM);

    conv_f16<<<8192, 256>>>((const float4*)Q, (const float4*)K,
                            (const float4*)d_in[2], (const float4*)d_in[4],
                            (const float4*)d_in[6], (const float4*)d_in[8]);
    // q projection: fp32 + bf16 outputs
    gemm3<<<dim3(8, 16), 256, G3SMEM>>>(pqi, pwq, nullptr, bq, nullptr,
                                        pq, pqh, nullptr, nullptr, 0);
    // fused k,v projection: bf16 outputs
    gemm3<<<dim3(16, 16), 256, G3SMEM>>>(pki, pwk, pwv, bk, bv,
                                         nullptr, pkh, pvh, nullptr, 1);
    attn_kernel<<<dim3(M_Q / 128, NH), 256>>>();
    // output projection with relu + residual
    gemm3<<<dim3(8, 16), 256, G3SMEM>>>(pah, pwo, nullptr, bo, nullptr,
                                        out, nullptr, nullptr, pa, 2);
}